// round 5
// baseline (speedup 1.0000x reference)
#include <cuda_runtime.h>
#include <math.h>
typedef unsigned long long ull;

#define VOCAB 10000
#define H 1024
#define H2 2048
#define BB 32
#define TT 128
#define MROWS (BB*TT)
#define NB 256
#define NTHR 256

// dynamic smem float offsets
#define A0_0 0
#define A0_1 4224
#define A1_0 8448
#define A1_1 12672
#define W_0  16896
#define W_1  19008
#define SMF  21120   // 84,480 bytes

// ---------------- device scratch ----------------
__device__ __align__(16) float g_x[MROWS*H];
__device__ __align__(16) float g_gx0[(size_t)TT*H2*BB];  // [t][n][m]
__device__ __align__(16) float g_cx0[(size_t)TT*H*BB];   // [t][n][m]
__device__ __align__(16) float g_outT[(size_t)TT*H*BB];  // [t][n][m]
__device__ __align__(16) float g_out2[(size_t)MROWS*H];
__device__ __align__(16) float g_h0m[2][BB*H];           // m-major ping-pong
__device__ __align__(16) float g_h1m[BB*H];
__device__ __align__(16) float g_rh0m[BB*H];
__device__ __align__(16) float g_rh1m[BB*H];
__device__ __align__(16) float g_u0[H*BB];               // [n][m]
__device__ __align__(16) float g_u1[H*BB];
__device__ __align__(16) float g_Tg0[(size_t)H2*H];      // [n][k] = Wg0[1024+k][n]
__device__ __align__(16) float g_Tg1[(size_t)H2*H2];     // [n][k] = Wg1[k][n]
__device__ __align__(16) float g_Tc0[(size_t)H*H];       // [n][k] = Wc0[1024+k][n]
__device__ __align__(16) float g_Tc1[(size_t)H*H2];      // [n][k] = Wc1[k][n]
__device__ volatile unsigned g_cnt;
__device__ volatile unsigned g_gen;

// ---------------- helpers ----------------
__device__ __forceinline__ ull pdup(float x){ ull r; asm("mov.b64 %0,{%1,%1};":"=l"(r):"f"(x)); return r; }
__device__ __forceinline__ ull f2fma(ull a,ull x,ull y){ ull d; asm("fma.rn.f32x2 %0,%1,%2,%3;":"=l"(d):"l"(x),"l"(y),"l"(a)); return d; }
__device__ __forceinline__ float plo(ull v){ return __uint_as_float((unsigned)v); }
__device__ __forceinline__ float phi(ull v){ return __uint_as_float((unsigned)(v>>32)); }
__device__ __forceinline__ float sigf(float x){ return __fdividef(1.f, 1.f+__expf(-x)); }
__device__ __forceinline__ float tanhx(float x){ return 1.f-__fdividef(2.f, __expf(2.f*x)+1.f); }

__device__ __forceinline__ void cp16(float* d, const float* s){
    unsigned ds = (unsigned)__cvta_generic_to_shared(d);
    asm volatile("cp.async.cg.shared.global [%0], [%1], 16;" :: "r"(ds), "l"(s) : "memory");
}
#define CP_COMMIT asm volatile("cp.async.commit_group;" ::: "memory")
#define CP_WAIT1  asm volatile("cp.async.wait_group 1;" ::: "memory")
#define CP_WAIT0  asm volatile("cp.async.wait_group 0;" ::: "memory")

__device__ __forceinline__ void gsync(){
    __syncthreads();
    if (threadIdx.x == 0){
        unsigned gen = g_gen;
        __threadfence();
        unsigned old = atomicAdd((unsigned*)&g_cnt, 1u);
        if (old == NB-1){ g_cnt = 0; __threadfence(); g_gen = gen+1; }
        else { while (g_gen == gen) { } }
    }
    __syncthreads();
}

// ---------------- utility kernels ----------------
__global__ void embed_k(const int* __restrict__ idx, const float* __restrict__ emb,
                        float* __restrict__ x){
    int row = blockIdx.x, tid = threadIdx.x;
    ((float4*)(x + (size_t)row*H))[tid] = ((const float4*)(emb + (size_t)idx[row]*H))[tid];
}

// dst[n][k] = src[srow0+k][n]
__global__ void tr_w(const float* __restrict__ src, int srow0, int ld,
                     float* __restrict__ dst, int ldd){
    __shared__ float s[32][33];
    int kb = blockIdx.x*32, nb = blockIdx.y*32;
    int tx = threadIdx.x, ty = threadIdx.y;
#pragma unroll
    for (int i=0;i<32;i+=8) s[ty+i][tx] = src[(size_t)(srow0+kb+ty+i)*ld + nb+tx];
    __syncthreads();
#pragma unroll
    for (int i=0;i<32;i+=8) dst[(size_t)(nb+ty+i)*ldd + kb+tx] = s[tx][ty+i];
}

__global__ void transp_out(const float* __restrict__ outT, float* __restrict__ out){
    __shared__ float s[32][33];
    int t = blockIdx.x, nb = blockIdx.y*32;
    int tx = threadIdx.x, ty = threadIdx.y;
#pragma unroll
    for (int i=0;i<32;i+=8) s[ty+i][tx] = outT[((size_t)t*H + nb+ty+i)*BB + tx];
    __syncthreads();
#pragma unroll
    for (int i=0;i<32;i+=8) out[((size_t)(ty+i)*TT + t)*H + nb+tx] = s[tx][ty+i];
}

// ---------------- big GEMM (f32x2) ----------------
template<bool BT, bool GRUL>
__global__ void gemm_big(const float* __restrict__ A, const float* __restrict__ Bm,
                         const float* __restrict__ bias, float* __restrict__ C,
                         int M, int N, int K, int ldb)
{
    __shared__ __align__(16) float As[16][132];
    __shared__ __align__(16) float Bs[16][68];
    int m0 = blockIdx.y*128, n0 = blockIdx.x*64, tid = threadIdx.x;
    int mm0 = (tid>>4)*8, nn0 = (tid&15)*4;
    ull acc2[4][4];
#pragma unroll
    for (int p=0;p<4;p++)
#pragma unroll
        for (int c=0;c<4;c++) acc2[p][c]=0ull;

    for (int k0=0;k0<K;k0+=16){
#pragma unroll
        for (int i=0;i<2;i++){
            int f = tid + i*256, am = f>>2, kq = f&3;
            float4 v = *(const float4*)(A + (size_t)(m0+am)*K + k0 + kq*4);
            As[kq*4+0][am]=v.x; As[kq*4+1][am]=v.y; As[kq*4+2][am]=v.z; As[kq*4+3][am]=v.w;
        }
        if (!BT){
            int brow = tid>>4, n = n0 + (tid&15)*4;
            float4 v;
            if (n+3 < N) v = *(const float4*)(Bm + (size_t)(k0+brow)*ldb + n);
            else {
                v.x=(n+0<N)?Bm[(size_t)(k0+brow)*ldb+n+0]:0.f;
                v.y=(n+1<N)?Bm[(size_t)(k0+brow)*ldb+n+1]:0.f;
                v.z=(n+2<N)?Bm[(size_t)(k0+brow)*ldb+n+2]:0.f;
                v.w=(n+3<N)?Bm[(size_t)(k0+brow)*ldb+n+3]:0.f;
            }
            *(float4*)&Bs[brow][(tid&15)*4] = v;
        } else {
            int nrow = tid>>2, kq = tid&3, n = n0+nrow;
            float4 v = make_float4(0.f,0.f,0.f,0.f);
            if (n < N) v = *(const float4*)(Bm + (size_t)n*ldb + k0 + kq*4);
            Bs[kq*4+0][nrow]=v.x; Bs[kq*4+1][nrow]=v.y; Bs[kq*4+2][nrow]=v.z; Bs[kq*4+3][nrow]=v.w;
        }
        __syncthreads();
#pragma unroll
        for (int kk=0;kk<16;kk++){
            ulonglong2 a01 = *(const ulonglong2*)&As[kk][mm0];
            ulonglong2 a23 = *(const ulonglong2*)&As[kk][mm0+4];
            float4 tb = *(const float4*)&Bs[kk][nn0];
            ull b0=pdup(tb.x), b1=pdup(tb.y), b2=pdup(tb.z), b3=pdup(tb.w);
            acc2[0][0]=f2fma(acc2[0][0],a01.x,b0); acc2[0][1]=f2fma(acc2[0][1],a01.x,b1);
            acc2[0][2]=f2fma(acc2[0][2],a01.x,b2); acc2[0][3]=f2fma(acc2[0][3],a01.x,b3);
            acc2[1][0]=f2fma(acc2[1][0],a01.y,b0); acc2[1][1]=f2fma(acc2[1][1],a01.y,b1);
            acc2[1][2]=f2fma(acc2[1][2],a01.y,b2); acc2[1][3]=f2fma(acc2[1][3],a01.y,b3);
            acc2[2][0]=f2fma(acc2[2][0],a23.x,b0); acc2[2][1]=f2fma(acc2[2][1],a23.x,b1);
            acc2[2][2]=f2fma(acc2[2][2],a23.x,b2); acc2[2][3]=f2fma(acc2[2][3],a23.x,b3);
            acc2[3][0]=f2fma(acc2[3][0],a23.y,b0); acc2[3][1]=f2fma(acc2[3][1],a23.y,b1);
            acc2[3][2]=f2fma(acc2[3][2],a23.y,b2); acc2[3][3]=f2fma(acc2[3][3],a23.y,b3);
        }
        __syncthreads();
    }
#pragma unroll
    for (int p=0;p<4;p++)
#pragma unroll
        for (int c=0;c<4;c++){
            int n = n0+nn0+c;
            if (n < N){
                float v0 = plo(acc2[p][c]), v1 = phi(acc2[p][c]);
                if (bias){ v0 += bias[n]; v1 += bias[n]; }
                int r0 = m0+mm0+2*p, r1 = r0+1;
                if (GRUL){
                    C[((size_t)(r0&(TT-1))*N + n)*BB + (r0>>7)] = v0;
                    C[((size_t)(r1&(TT-1))*N + n)*BB + (r1>>7)] = v1;
                } else {
                    C[(size_t)r0*N + n] = v0;
                    C[(size_t)r1*N + n] = v1;
                }
            }
        }
}

// ---------------- persistent recurrence ----------------
__global__ void __launch_bounds__(NTHR, 2)
rnn_persist(const float* __restrict__ bg0, const float* __restrict__ bc0,
            const float* __restrict__ bg1, const float* __restrict__ bc1)
{
    extern __shared__ __align__(16) float sm[];
    const int tid = threadIdx.x, c = blockIdx.x;
    const int gt = c*NTHR + tid;
    if (gt < BB*H){ g_h0m[0][gt] = 0.f; g_h1m[gt] = 0.f; }
    gsync();

    // phase A: (col 0..15, m-pair 0..15); col<8 -> layer0 gates, col>=8 -> layer1
    const int colA = tid>>4, mp = tid&15;
    const bool aL0 = colA < 8;
    const int nA = c*8 + (aL0 ? colA : colA-8);
    // phase B: (col 0..7, m 0..31); col<4 -> layer0 cand, col>=4 -> layer1
    const int colB = tid>>5, mB = tid&31;
    const bool bL0 = colB < 4;
    const int nB = c*4 + (bL0 ? colB : colB-4);

    int cur = 0;
    for (int t = 0; t <= TT; t++){
        const bool do0 = (t < TT), do1 = (t > 0);
        const float* __restrict__ h0c = g_h0m[cur];
        float* __restrict__ h0p = g_h0m[cur^1];
        const int nc = do1 ? 16 : 8;

        // ================ PHASE A: gates ================
        {
            auto stage = [&](int kc){
                float* Ab = sm + ((kc&1) ? A0_1 : A0_0);
                const float* As2 = (kc < 8) ? h0c + kc*128 : g_h1m + (kc-8)*128;
                #pragma unroll
                for (int u=0;u<4;u++){ int e = tid + u*256; int m = e>>5, g = e&31;
                    cp16(Ab + m*132 + g*4, As2 + m*H + g*4); }
                float* Wb = sm + ((kc&1) ? W_1 : W_0);
                #pragma unroll
                for (int u=0;u<2;u++){ int e = tid + u*256; int cl = e>>5, g = e&31;
                    if (kc < 8 || cl >= 8){
                        const float* ws = (cl < 8)
                            ? g_Tg0 + (size_t)(c*8+cl)*H + kc*128
                            : g_Tg1 + (size_t)(c*8+cl-8)*H2 + kc*128;
                        cp16(Wb + cl*132 + g*4, ws + g*4);
                    } }
            };
            stage(0); CP_COMMIT;
            ull a00=0,a01=0,a10=0,a11=0;
            for (int kc=0;kc<nc;kc++){
                if (kc+1 < nc){ stage(kc+1); CP_COMMIT; CP_WAIT1; } else CP_WAIT0;
                __syncthreads();
                const bool act = aL0 ? (do0 && kc < 8) : do1;
                if (act){
                    const float* Ap = sm + ((kc&1)?A0_1:A0_0) + (2*mp)*132;
                    const float* Wp = sm + ((kc&1)?W_1:W_0) + colA*132;
                    #pragma unroll 8
                    for (int q=0;q<32;q++){
                        ulonglong2 w  = *(const ulonglong2*)(Wp + q*4);
                        ulonglong2 x0 = *(const ulonglong2*)(Ap + q*4);
                        ulonglong2 x1 = *(const ulonglong2*)(Ap + 132 + q*4);
                        a00 = f2fma(a00, x0.x, w.x); a01 = f2fma(a01, x0.y, w.y);
                        a10 = f2fma(a10, x1.x, w.x); a11 = f2fma(a11, x1.y, w.y);
                    }
                }
                __syncthreads();
            }
            if (aL0 ? do0 : do1){
                int m0 = 2*mp;
                float v0 = plo(a00)+phi(a00)+plo(a01)+phi(a01);
                float v1 = plo(a10)+phi(a10)+plo(a11)+phi(a11);
                if (aL0){
                    float2 pre = *(const float2*)(g_gx0 + ((size_t)t*H2 + nA)*BB + m0);
                    float b = bg0[nA];
                    float g0 = sigf(v0 + pre.x + b), g1 = sigf(v1 + pre.y + b);
                    if (nA < H){
                        g_rh0m[m0*H + nA]     = g0 * h0c[m0*H + nA];
                        g_rh0m[(m0+1)*H + nA] = g1 * h0c[(m0+1)*H + nA];
                    } else { float2 gg = {g0,g1}; *(float2*)(g_u0 + (nA-H)*BB + m0) = gg; }
                } else {
                    float b = bg1[nA];
                    float g0 = sigf(v0 + b), g1 = sigf(v1 + b);
                    if (nA < H){
                        g_rh1m[m0*H + nA]     = g0 * g_h1m[m0*H + nA];
                        g_rh1m[(m0+1)*H + nA] = g1 * g_h1m[(m0+1)*H + nA];
                    } else { float2 gg = {g0,g1}; *(float2*)(g_u1 + (nA-H)*BB + m0) = gg; }
                }
            }
        }
        gsync();

        // ================ PHASE B: candidates + update ================
        {
            auto stage = [&](int kc){
                if (kc < 8){
                    float* Ab = sm + ((kc&1) ? A0_1 : A0_0);
                    const float* As2 = g_rh0m + kc*128;
                    #pragma unroll
                    for (int u=0;u<4;u++){ int e = tid + u*256; int m = e>>5, g = e&31;
                        cp16(Ab + m*132 + g*4, As2 + m*H + g*4); }
                }
                float* A1b = sm + ((kc&1) ? A1_1 : A1_0);
                const float* A1s = (kc < 8) ? h0c + kc*128 : g_rh1m + (kc-8)*128;
                #pragma unroll
                for (int u=0;u<4;u++){ int e = tid + u*256; int m = e>>5, g = e&31;
                    cp16(A1b + m*132 + g*4, A1s + m*H + g*4); }
                { int cl = tid>>5, g = tid&31;
                  if (kc < 8 || cl >= 4){
                      const float* ws = (cl < 4)
                          ? g_Tc0 + (size_t)(c*4+cl)*H + kc*128
                          : g_Tc1 + (size_t)(c*4+cl-4)*H2 + kc*128;
                      cp16(sm + ((kc&1)?W_1:W_0) + cl*132 + g*4, ws + g*4);
                  } }
            };
            stage(0); CP_COMMIT;
            ull pa=0, pb=0;
            for (int kc=0;kc<nc;kc++){
                if (kc+1 < nc){ stage(kc+1); CP_COMMIT; CP_WAIT1; } else CP_WAIT0;
                __syncthreads();
                const bool act = bL0 ? (do0 && kc < 8) : do1;
                if (act){
                    const float* Ap = sm + (bL0 ? ((kc&1)?A0_1:A0_0) : ((kc&1)?A1_1:A1_0)) + mB*132;
                    const float* Wp = sm + ((kc&1)?W_1:W_0) + colB*132;
                    #pragma unroll 8
                    for (int q=0;q<32;q++){
                        ulonglong2 w = *(const ulonglong2*)(Wp + q*4);
                        ulonglong2 x = *(const ulonglong2*)(Ap + q*4);
                        pa = f2fma(pa, x.x, w.x); pb = f2fma(pb, x.y, w.y);
                    }
                }
                __syncthreads();
            }
            if (bL0 ? do0 : do1){
                float v = plo(pa)+phi(pa)+plo(pb)+phi(pb);
                if (bL0){
                    v += g_cx0[((size_t)t*H + nB)*BB + mB] + bc0[nB];
                    float cc = tanhx(v);
                    float u = g_u0[nB*BB + mB];
                    float h = h0c[mB*H + nB];
                    h0p[mB*H + nB] = u*h + (1.f-u)*cc;
                } else {
                    v += bc1[nB];
                    float cc = tanhx(v);
                    float u = g_u1[nB*BB + mB];
                    float h = g_h1m[mB*H + nB];
                    float hn = u*h + (1.f-u)*cc;
                    g_h1m[mB*H + nB] = hn;
                    g_outT[((size_t)(t-1)*H + nB)*BB + mB] = hn;
                }
            }
        }
        cur ^= 1;
        gsync();
    }
}

// ---------------- launch ----------------
extern "C" void kernel_launch(void* const* d_in, const int* in_sizes, int n_in,
                              void* d_out, int out_size)
{
    const int*   idx = (const int*)  d_in[0];
    const float* emb = (const float*)d_in[1];
    const float* Wg0 = (const float*)d_in[2];
    const float* bg0 = (const float*)d_in[3];
    const float* Wc0 = (const float*)d_in[4];
    const float* bc0 = (const float*)d_in[5];
    const float* Wg1 = (const float*)d_in[6];
    const float* bg1 = (const float*)d_in[7];
    const float* Wc1 = (const float*)d_in[8];
    const float* bc1 = (const float*)d_in[9];
    const float* smb = (const float*)d_in[10];
    float* out = (float*)d_out;

    float *px,*pgx0,*pcx0,*poutT,*pout2,*pTg0,*pTg1,*pTc0,*pTc1;
    cudaGetSymbolAddress((void**)&px,    g_x);
    cudaGetSymbolAddress((void**)&pgx0,  g_gx0);
    cudaGetSymbolAddress((void**)&pcx0,  g_cx0);
    cudaGetSymbolAddress((void**)&poutT, g_outT);
    cudaGetSymbolAddress((void**)&pout2, g_out2);
    cudaGetSymbolAddress((void**)&pTg0,  g_Tg0);
    cudaGetSymbolAddress((void**)&pTg1,  g_Tg1);
    cudaGetSymbolAddress((void**)&pTc0,  g_Tc0);
    cudaGetSymbolAddress((void**)&pTc1,  g_Tc1);

    static bool attr_set = false;
    if (!attr_set){
        cudaFuncSetAttribute(rnn_persist, cudaFuncAttributeMaxDynamicSharedMemorySize, SMF*4);
        attr_set = true;
    }

    // weight transposes: [n][k]
    tr_w<<<dim3(32,64), dim3(32,8)>>>(Wg0, 1024, H2, pTg0, H);
    tr_w<<<dim3(64,64), dim3(32,8)>>>(Wg1, 0,    H2, pTg1, H2);
    tr_w<<<dim3(32,32), dim3(32,8)>>>(Wc0, 1024, H,  pTc0, H);
    tr_w<<<dim3(64,32), dim3(32,8)>>>(Wc1, 0,    H,  pTc1, H2);

    embed_k<<<MROWS, 256>>>(idx, emb, px);

    // layer-0 x-projections -> [t][n][m]
    gemm_big<false,true><<<dim3(H2/64, MROWS/128), 256>>>(px, Wg0, nullptr, pgx0, MROWS, H2, H, H2);
    gemm_big<false,true><<<dim3(H/64,  MROWS/128), 256>>>(px, Wc0, nullptr, pcx0, MROWS, H, H, H);

    // pipelined recurrence
    rnn_persist<<<NB, NTHR, SMF*4>>>(bg0, bc0, bg1, bc1);

    // reorder + tied-softmax logits
    transp_out<<<dim3(TT, H/32), dim3(32,8)>>>(poutT, pout2);
    gemm_big<true,false><<<dim3((VOCAB+63)/64, MROWS/128), 256>>>(pout2, emb, smb, out, MROWS, VOCAB, H, H);
}

// round 6
// speedup vs baseline: 1.7391x; 1.7391x over previous
#include <cuda_runtime.h>
#include <math.h>
typedef unsigned long long ull;

#define VOCAB 10000
#define H 1024
#define H2 2048
#define BB 32
#define TT 128
#define MROWS (BB*TT)
#define NB 128
#define NTHR 512

// dynamic smem float offsets
#define OA    0        // phase A: A double buffer 2x8320
#define OW    16640    // phase A: W double buffer 2x8320
#define OB_A0 0        // phase B: A0 (rh0)
#define OB_A1 16640    // phase B: A1 (h0 / rh1)
#define OB_W  33280    // phase B: W 2x4160
#define ORED  41600    // reduction buffer 8192
#define SMF   49792    // 199168 bytes

// ---------------- device scratch ----------------
__device__ __align__(16) float g_x[MROWS*H];
__device__ __align__(16) float g_gx0[(size_t)TT*BB*H2];  // [t][m][n]
__device__ __align__(16) float g_cx0[(size_t)TT*BB*H];   // [t][m][n]
__device__ __align__(16) float g_outT[(size_t)TT*BB*H];  // [t][m][n]
__device__ __align__(16) float g_out2[(size_t)MROWS*H];  // [m*T+t][n]
__device__ __align__(16) float g_h0m[2][BB*H];           // [m][n] ping-pong
__device__ __align__(16) float g_h1m[BB*H];
__device__ __align__(16) float g_rh0m[BB*H];
__device__ __align__(16) float g_rh1m[BB*H];
__device__ __align__(16) float g_u0m[BB*H];
__device__ __align__(16) float g_u1m[BB*H];
__device__ __align__(16) float g_Tg0[(size_t)H2*H];      // [n][k] = Wg0[1024+k][n]
__device__ __align__(16) float g_Tg1[(size_t)H2*H2];     // [n][k] = Wg1[k][n]
__device__ __align__(16) float g_Tc0[(size_t)H*H];       // [n][k] = Wc0[1024+k][n]
__device__ __align__(16) float g_Tc1[(size_t)H*H2];      // [n][k] = Wc1[k][n]
__device__ volatile unsigned g_cnt;
__device__ volatile unsigned g_gen;

// ---------------- helpers ----------------
__device__ __forceinline__ ull pdup(float x){ ull r; asm("mov.b64 %0,{%1,%1};":"=l"(r):"f"(x)); return r; }
__device__ __forceinline__ ull f2fma(ull a,ull x,ull y){ ull d; asm("fma.rn.f32x2 %0,%1,%2,%3;":"=l"(d):"l"(x),"l"(y),"l"(a)); return d; }
__device__ __forceinline__ float plo(ull v){ return __uint_as_float((unsigned)v); }
__device__ __forceinline__ float phi(ull v){ return __uint_as_float((unsigned)(v>>32)); }
__device__ __forceinline__ float sigf(float x){ return __fdividef(1.f, 1.f+__expf(-x)); }
__device__ __forceinline__ float tanhx(float x){ return 1.f-__fdividef(2.f, __expf(2.f*x)+1.f); }

__device__ __forceinline__ void cp16(float* d, const float* s){
    unsigned ds = (unsigned)__cvta_generic_to_shared(d);
    asm volatile("cp.async.cg.shared.global [%0], [%1], 16;" :: "r"(ds), "l"(s) : "memory");
}
#define CP_COMMIT asm volatile("cp.async.commit_group;" ::: "memory")
#define CP_WAIT1  asm volatile("cp.async.wait_group 1;" ::: "memory")
#define CP_WAIT0  asm volatile("cp.async.wait_group 0;" ::: "memory")

__device__ __forceinline__ void gsync(){
    __threadfence();
    __syncthreads();
    if (threadIdx.x == 0){
        unsigned gen = g_gen;
        unsigned old = atomicAdd((unsigned*)&g_cnt, 1u);
        if (old == NB-1){ g_cnt = 0; __threadfence(); g_gen = gen+1; }
        else { while (g_gen == gen) { } }
    }
    __syncthreads();
}

// ---------------- utility kernels ----------------
__global__ void embed_k(const int* __restrict__ idx, const float* __restrict__ emb,
                        float* __restrict__ x){
    int row = blockIdx.x, tid = threadIdx.x;
    ((float4*)(x + (size_t)row*H))[tid] = ((const float4*)(emb + (size_t)idx[row]*H))[tid];
}

// dst[n][k] = src[srow0+k][n]
__global__ void tr_w(const float* __restrict__ src, int srow0, int ld,
                     float* __restrict__ dst, int ldd){
    __shared__ float s[32][33];
    int kb = blockIdx.x*32, nb = blockIdx.y*32;
    int tx = threadIdx.x, ty = threadIdx.y;
#pragma unroll
    for (int i=0;i<32;i+=8) s[ty+i][tx] = src[(size_t)(srow0+kb+ty+i)*ld + nb+tx];
    __syncthreads();
#pragma unroll
    for (int i=0;i<32;i+=8) dst[(size_t)(nb+ty+i)*ldd + kb+tx] = s[tx][ty+i];
}

// out2[m*T+t][n] = outT[t][m][n]
__global__ void copy_out(const float* __restrict__ outT, float* __restrict__ out2){
    int r = blockIdx.x;                   // m*128 + t
    int m = r>>7, t = r&127;
    ((float4*)(out2 + (size_t)r*H))[threadIdx.x] =
        ((const float4*)(outT + ((size_t)t*BB + m)*H))[threadIdx.x];
}

// ---------------- big GEMM (f32x2) ----------------
// BT=false: B row-major [K,N]. BT=true: B row-major [N,K] (ldb=K).
// GRUL=true: rows r = b*T+t, write C[(t*32+b)*N + n].
template<bool BT, bool GRUL>
__global__ void gemm_big(const float* __restrict__ A, const float* __restrict__ Bm,
                         const float* __restrict__ bias, float* __restrict__ C,
                         int M, int N, int K, int ldb)
{
    __shared__ __align__(16) float As[16][132];
    __shared__ __align__(16) float Bs[16][68];
    int m0 = blockIdx.y*128, n0 = blockIdx.x*64, tid = threadIdx.x;
    int mm0 = (tid>>4)*8, nn0 = (tid&15)*4;
    ull acc2[4][4];
#pragma unroll
    for (int p=0;p<4;p++)
#pragma unroll
        for (int c2=0;c2<4;c2++) acc2[p][c2]=0ull;

    for (int k0=0;k0<K;k0+=16){
#pragma unroll
        for (int i=0;i<2;i++){
            int f = tid + i*256, am = f>>2, kq = f&3;
            float4 v = *(const float4*)(A + (size_t)(m0+am)*K + k0 + kq*4);
            As[kq*4+0][am]=v.x; As[kq*4+1][am]=v.y; As[kq*4+2][am]=v.z; As[kq*4+3][am]=v.w;
        }
        if (!BT){
            int brow = tid>>4, n = n0 + (tid&15)*4;
            float4 v;
            if (n+3 < N) v = *(const float4*)(Bm + (size_t)(k0+brow)*ldb + n);
            else {
                v.x=(n+0<N)?Bm[(size_t)(k0+brow)*ldb+n+0]:0.f;
                v.y=(n+1<N)?Bm[(size_t)(k0+brow)*ldb+n+1]:0.f;
                v.z=(n+2<N)?Bm[(size_t)(k0+brow)*ldb+n+2]:0.f;
                v.w=(n+3<N)?Bm[(size_t)(k0+brow)*ldb+n+3]:0.f;
            }
            *(float4*)&Bs[brow][(tid&15)*4] = v;
        } else {
            int nrow = tid>>2, kq = tid&3, n = n0+nrow;
            float4 v = make_float4(0.f,0.f,0.f,0.f);
            if (n < N) v = *(const float4*)(Bm + (size_t)n*ldb + k0 + kq*4);
            Bs[kq*4+0][nrow]=v.x; Bs[kq*4+1][nrow]=v.y; Bs[kq*4+2][nrow]=v.z; Bs[kq*4+3][nrow]=v.w;
        }
        __syncthreads();
#pragma unroll
        for (int kk=0;kk<16;kk++){
            ulonglong2 a01 = *(const ulonglong2*)&As[kk][mm0];
            ulonglong2 a23 = *(const ulonglong2*)&As[kk][mm0+4];
            float4 tb = *(const float4*)&Bs[kk][nn0];
            ull b0=pdup(tb.x), b1=pdup(tb.y), b2=pdup(tb.z), b3=pdup(tb.w);
            acc2[0][0]=f2fma(acc2[0][0],a01.x,b0); acc2[0][1]=f2fma(acc2[0][1],a01.x,b1);
            acc2[0][2]=f2fma(acc2[0][2],a01.x,b2); acc2[0][3]=f2fma(acc2[0][3],a01.x,b3);
            acc2[1][0]=f2fma(acc2[1][0],a01.y,b0); acc2[1][1]=f2fma(acc2[1][1],a01.y,b1);
            acc2[1][2]=f2fma(acc2[1][2],a01.y,b2); acc2[1][3]=f2fma(acc2[1][3],a01.y,b3);
            acc2[2][0]=f2fma(acc2[2][0],a23.x,b0); acc2[2][1]=f2fma(acc2[2][1],a23.x,b1);
            acc2[2][2]=f2fma(acc2[2][2],a23.x,b2); acc2[2][3]=f2fma(acc2[2][3],a23.x,b3);
            acc2[3][0]=f2fma(acc2[3][0],a23.y,b0); acc2[3][1]=f2fma(acc2[3][1],a23.y,b1);
            acc2[3][2]=f2fma(acc2[3][2],a23.y,b2); acc2[3][3]=f2fma(acc2[3][3],a23.y,b3);
        }
        __syncthreads();
    }
#pragma unroll
    for (int p=0;p<4;p++)
#pragma unroll
        for (int c2=0;c2<4;c2++){
            int n = n0+nn0+c2;
            if (n < N){
                float v0 = plo(acc2[p][c2]), v1 = phi(acc2[p][c2]);
                if (bias){ v0 += bias[n]; v1 += bias[n]; }
                int r0 = m0+mm0+2*p, r1 = r0+1;
                if (GRUL){
                    C[((size_t)((r0&127)*BB + (r0>>7)))*N + n] = v0;
                    C[((size_t)((r1&127)*BB + (r1>>7)))*N + n] = v1;
                } else {
                    C[(size_t)r0*N + n] = v0;
                    C[(size_t)r1*N + n] = v1;
                }
            }
        }
}

// ---------------- persistent recurrence ----------------
__global__ void __launch_bounds__(NTHR, 1)
rnn_persist(const float* __restrict__ bg0, const float* __restrict__ bc0,
            const float* __restrict__ bg1, const float* __restrict__ bc1)
{
    extern __shared__ __align__(16) float sm[];
    const int tid = threadIdx.x, c = blockIdx.x;

    for (int i = c*NTHR + tid; i < BB*H; i += NB*NTHR){ g_h0m[0][i] = 0.f; g_h1m[i] = 0.f; }
    gsync();

    // phase A: ks(8) slow, gid(64)=[ls2|cs4|ms8] fast
    const int ksA = tid>>6, gidA = tid&63;
    const int lsA = gidA>>5, csA = (gidA>>3)&3, msA = gidA&7;
    const int wbaseA = (lsA*16 + csA*4)*260;
    // phase B: ks(16) slow, gid(32)=[ls2|cs2|ms8] fast
    const int ksB = tid>>5, gidB = tid&31;
    const int lsB = gidB>>4, csB = (gidB>>3)&1, msB = gidB&7;
    const int wbaseB = (lsB*8 + csB*4)*260;

    float* red = sm + ORED;
    int cur = 0;

    for (int t = 0; t <= TT; t++){
        const bool do0 = (t < TT), do1 = (t > 0);
        const float* __restrict__ h0c = g_h0m[cur];
        float* __restrict__ h0p = g_h0m[cur^1];
        const int nc = do1 ? 8 : 4;

        // ================= PHASE A: gates =================
        {
            auto stage = [&](int kc){
                float* Ab = sm + OA + (kc&1)*8320;
                const float* src = (kc < 4) ? h0c + kc*256 : g_h1m + (kc-4)*256;
                #pragma unroll
                for (int u=0;u<4;u++){ int e = tid + u*NTHR; int m = e>>6, g4 = e&63;
                    cp16(Ab + m*260 + g4*4, src + m*H + g4*4); }
                float* Wb = sm + OW + (kc&1)*8320;
                if (kc < 4){
                    #pragma unroll
                    for (int u=0;u<4;u++){ int e = tid + u*NTHR; int wr = e>>6, g4 = e&63;
                        const float* ws = (wr < 16)
                            ? g_Tg0 + (size_t)(c*16+wr)*H + kc*256
                            : g_Tg1 + (size_t)(c*16+wr-16)*H2 + kc*256;
                        cp16(Wb + wr*260 + g4*4, ws + g4*4); }
                } else {
                    #pragma unroll
                    for (int u=0;u<2;u++){ int e = tid + u*NTHR; int wr = 16 + (e>>6), g4 = e&63;
                        cp16(Wb + wr*260 + g4*4,
                             g_Tg1 + (size_t)(c*16+wr-16)*H2 + 1024 + (kc-4)*256 + g4*4); }
                }
            };
            stage(0); CP_COMMIT;
            ull acc[4][4];
            #pragma unroll
            for (int mi=0;mi<4;mi++)
            #pragma unroll
                for (int ci=0;ci<4;ci++) acc[mi][ci] = 0ull;

            for (int kc=0;kc<nc;kc++){
                if (kc+1 < nc){ stage(kc+1); CP_COMMIT; CP_WAIT1; } else CP_WAIT0;
                __syncthreads();
                const bool act = (lsA==0) ? (do0 && kc < 4) : do1;
                if (act){
                    const float* Ab = sm + OA + (kc&1)*8320;
                    const float* Wb = sm + OW + (kc&1)*8320 + wbaseA;
                    #pragma unroll
                    for (int i=0;i<8;i++){
                        int ko = ksA*32 + i*4;
                        ulonglong2 w0 = *(const ulonglong2*)(Wb + ko);
                        ulonglong2 w1 = *(const ulonglong2*)(Wb + 260 + ko);
                        ulonglong2 w2 = *(const ulonglong2*)(Wb + 520 + ko);
                        ulonglong2 w3 = *(const ulonglong2*)(Wb + 780 + ko);
                        ulonglong2 a0 = *(const ulonglong2*)(Ab + msA*260 + ko);
                        ulonglong2 a1 = *(const ulonglong2*)(Ab + (msA+8)*260 + ko);
                        ulonglong2 a2 = *(const ulonglong2*)(Ab + (msA+16)*260 + ko);
                        ulonglong2 a3 = *(const ulonglong2*)(Ab + (msA+24)*260 + ko);
                        acc[0][0]=f2fma(f2fma(acc[0][0],a0.x,w0.x),a0.y,w0.y);
                        acc[0][1]=f2fma(f2fma(acc[0][1],a0.x,w1.x),a0.y,w1.y);
                        acc[0][2]=f2fma(f2fma(acc[0][2],a0.x,w2.x),a0.y,w2.y);
                        acc[0][3]=f2fma(f2fma(acc[0][3],a0.x,w3.x),a0.y,w3.y);
                        acc[1][0]=f2fma(f2fma(acc[1][0],a1.x,w0.x),a1.y,w0.y);
                        acc[1][1]=f2fma(f2fma(acc[1][1],a1.x,w1.x),a1.y,w1.y);
                        acc[1][2]=f2fma(f2fma(acc[1][2],a1.x,w2.x),a1.y,w2.y);
                        acc[1][3]=f2fma(f2fma(acc[1][3],a1.x,w3.x),a1.y,w3.y);
                        acc[2][0]=f2fma(f2fma(acc[2][0],a2.x,w0.x),a2.y,w0.y);
                        acc[2][1]=f2fma(f2fma(acc[2][1],a2.x,w1.x),a2.y,w1.y);
                        acc[2][2]=f2fma(f2fma(acc[2][2],a2.x,w2.x),a2.y,w2.y);
                        acc[2][3]=f2fma(f2fma(acc[2][3],a2.x,w3.x),a2.y,w3.y);
                        acc[3][0]=f2fma(f2fma(acc[3][0],a3.x,w0.x),a3.y,w0.y);
                        acc[3][1]=f2fma(f2fma(acc[3][1],a3.x,w1.x),a3.y,w1.y);
                        acc[3][2]=f2fma(f2fma(acc[3][2],a3.x,w2.x),a3.y,w2.y);
                        acc[3][3]=f2fma(f2fma(acc[3][3],a3.x,w3.x),a3.y,w3.y);
                    }
                }
                __syncthreads();
            }
            // k-split reduction
            #pragma unroll
            for (int mi=0;mi<4;mi++)
            #pragma unroll
                for (int ci=0;ci<4;ci++)
                    red[(gidA*16 + mi*4 + ci)*8 + ksA] = plo(acc[mi][ci]) + phi(acc[mi][ci]);
            __syncthreads();
            #pragma unroll
            for (int q=0;q<2;q++){
                int V = tid*2 + q;
                int gid = V>>4, v = V&15;
                int ls = gid>>5, cs = (gid>>3)&3, ms = gid&7;
                int mi = v>>2, ci = v&3;
                int m = ms + 8*mi;
                int n = c*16 + cs*4 + ci;
                const float* rp = red + (gid*16+v)*8;
                float4 s0 = *(const float4*)rp;
                float4 s1 = *(const float4*)(rp+4);
                float sum = s0.x+s0.y+s0.z+s0.w+s1.x+s1.y+s1.z+s1.w;
                if (ls==0 && do0){
                    sum += g_gx0[((size_t)t*BB + m)*H2 + n] + bg0[n];
                    float g = sigf(sum);
                    if (c < 64) g_rh0m[m*H + n] = g * h0c[m*H + n];
                    else        g_u0m[m*H + n - 1024] = g;
                } else if (ls==1 && do1){
                    sum += bg1[n];
                    float g = sigf(sum);
                    if (c < 64) g_rh1m[m*H + n] = g * g_h1m[m*H + n];
                    else        g_u1m[m*H + n - 1024] = g;
                }
            }
        }
        gsync();

        // ================= PHASE B: candidates + update =================
        {
            auto stage = [&](int kc){
                if (do0 && kc < 4){
                    float* A0b = sm + OB_A0 + (kc&1)*8320;
                    const float* s0 = g_rh0m + kc*256;
                    #pragma unroll
                    for (int u=0;u<4;u++){ int e = tid + u*NTHR; int m = e>>6, g4 = e&63;
                        cp16(A0b + m*260 + g4*4, s0 + m*H + g4*4); }
                }
                float* A1b = sm + OB_A1 + (kc&1)*8320;
                const float* s1 = (kc < 4) ? h0c + kc*256 : g_rh1m + (kc-4)*256;
                #pragma unroll
                for (int u=0;u<4;u++){ int e = tid + u*NTHR; int m = e>>6, g4 = e&63;
                    cp16(A1b + m*260 + g4*4, s1 + m*H + g4*4); }
                float* Wb = sm + OB_W + (kc&1)*4160;
                if (kc < 4){
                    #pragma unroll
                    for (int u=0;u<2;u++){ int e = tid + u*NTHR; int wr = e>>6, g4 = e&63;
                        const float* ws = (wr < 8)
                            ? g_Tc0 + (size_t)(c*8+wr)*H + kc*256
                            : g_Tc1 + (size_t)(c*8+wr-8)*H2 + kc*256;
                        cp16(Wb + wr*260 + g4*4, ws + g4*4); }
                } else {
                    { int wr = 8 + (tid>>6), g4 = tid&63;
                      cp16(Wb + wr*260 + g4*4,
                           g_Tc1 + (size_t)(c*8+wr-8)*H2 + 1024 + (kc-4)*256 + g4*4); }
                }
            };
            stage(0); CP_COMMIT;
            ull acc[4][4];
            #pragma unroll
            for (int mi=0;mi<4;mi++)
            #pragma unroll
                for (int ci=0;ci<4;ci++) acc[mi][ci] = 0ull;

            for (int kc=0;kc<nc;kc++){
                if (kc+1 < nc){ stage(kc+1); CP_COMMIT; CP_WAIT1; } else CP_WAIT0;
                __syncthreads();
                const bool act = (lsB==0) ? (do0 && kc < 4) : do1;
                if (act){
                    const float* Ab = sm + (lsB ? OB_A1 : OB_A0) + (kc&1)*8320;
                    const float* Wb = sm + OB_W + (kc&1)*4160 + wbaseB;
                    #pragma unroll
                    for (int i=0;i<4;i++){
                        int ko = ksB*16 + i*4;
                        ulonglong2 w0 = *(const ulonglong2*)(Wb + ko);
                        ulonglong2 w1 = *(const ulonglong2*)(Wb + 260 + ko);
                        ulonglong2 w2 = *(const ulonglong2*)(Wb + 520 + ko);
                        ulonglong2 w3 = *(const ulonglong2*)(Wb + 780 + ko);
                        ulonglong2 a0 = *(const ulonglong2*)(Ab + msB*260 + ko);
                        ulonglong2 a1 = *(const ulonglong2*)(Ab + (msB+8)*260 + ko);
                        ulonglong2 a2 = *(const ulonglong2*)(Ab + (msB+16)*260 + ko);
                        ulonglong2 a3 = *(const ulonglong2*)(Ab + (msB+24)*260 + ko);
                        acc[0][0]=f2fma(f2fma(acc[0][0],a0.x,w0.x),a0.y,w0.y);
                        acc[0][1]=f2fma(f2fma(acc[0][1],a0.x,w1.x),a0.y,w1.y);
                        acc[0][2]=f2fma(f2fma(acc[0][2],a0.x,w2.x),a0.y,w2.y);
                        acc[0][3]=f2fma(f2fma(acc[0][3],a0.x,w3.x),a0.y,w3.y);
                        acc[1][0]=f2fma(f2fma(acc[1][0],a1.x,w0.x),a1.y,w0.y);
                        acc[1][1]=f2fma(f2fma(acc[1][1],a1.x,w1.x),a1.y,w1.y);
                        acc[1][2]=f2fma(f2fma(acc[1][2],a1.x,w2.x),a1.y,w2.y);
                        acc[1][3]=f2fma(f2fma(acc[1][3],a1.x,w3.x),a1.y,w3.y);
                        acc[2][0]=f2fma(f2fma(acc[2][0],a2.x,w0.x),a2.y,w0.y);
                        acc[2][1]=f2fma(f2fma(acc[2][1],a2.x,w1.x),a2.y,w1.y);
                        acc[2][2]=f2fma(f2fma(acc[2][2],a2.x,w2.x),a2.y,w2.y);
                        acc[2][3]=f2fma(f2fma(acc[2][3],a2.x,w3.x),a2.y,w3.y);
                        acc[3][0]=f2fma(f2fma(acc[3][0],a3.x,w0.x),a3.y,w0.y);
                        acc[3][1]=f2fma(f2fma(acc[3][1],a3.x,w1.x),a3.y,w1.y);
                        acc[3][2]=f2fma(f2fma(acc[3][2],a3.x,w2.x),a3.y,w2.y);
                        acc[3][3]=f2fma(f2fma(acc[3][3],a3.x,w3.x),a3.y,w3.y);
                    }
                }
                __syncthreads();
            }
            #pragma unroll
            for (int mi=0;mi<4;mi++)
            #pragma unroll
                for (int ci=0;ci<4;ci++)
                    red[(gidB*16 + mi*4 + ci)*16 + ksB] = plo(acc[mi][ci]) + phi(acc[mi][ci]);
            __syncthreads();
            {
                int V = tid;
                int gid = V>>4, v = V&15;
                int ls = gid>>4, cs = (gid>>3)&1, ms = gid&7;
                int mi = v>>2, ci = v&3;
                int m = ms + 8*mi;
                int n = c*8 + cs*4 + ci;
                const float* rp = red + (gid*16+v)*16;
                float4 s0 = *(const float4*)rp;
                float4 s1 = *(const float4*)(rp+4);
                float4 s2 = *(const float4*)(rp+8);
                float4 s3 = *(const float4*)(rp+12);
                float sum = s0.x+s0.y+s0.z+s0.w+s1.x+s1.y+s1.z+s1.w
                          + s2.x+s2.y+s2.z+s2.w+s3.x+s3.y+s3.z+s3.w;
                if (ls==0 && do0){
                    sum += g_cx0[((size_t)t*BB + m)*H + n] + bc0[n];
                    float cc = tanhx(sum);
                    float u = g_u0m[m*H + n];
                    float h = h0c[m*H + n];
                    h0p[m*H + n] = u*h + (1.f-u)*cc;
                } else if (ls==1 && do1){
                    sum += bc1[n];
                    float cc = tanhx(sum);
                    float u = g_u1m[m*H + n];
                    float h = g_h1m[m*H + n];
                    float hn = u*h + (1.f-u)*cc;
                    g_h1m[m*H + n] = hn;
                    g_outT[((size_t)(t-1)*BB + m)*H + n] = hn;
                }
            }
        }
        cur ^= 1;
        gsync();
    }
}

// ---------------- launch ----------------
extern "C" void kernel_launch(void* const* d_in, const int* in_sizes, int n_in,
                              void* d_out, int out_size)
{
    const int*   idx = (const int*)  d_in[0];
    const float* emb = (const float*)d_in[1];
    const float* Wg0 = (const float*)d_in[2];
    const float* bg0 = (const float*)d_in[3];
    const float* Wc0 = (const float*)d_in[4];
    const float* bc0 = (const float*)d_in[5];
    const float* Wg1 = (const float*)d_in[6];
    const float* bg1 = (const float*)d_in[7];
    const float* Wc1 = (const float*)d_in[8];
    const float* bc1 = (const float*)d_in[9];
    const float* smb = (const float*)d_in[10];
    float* out = (float*)d_out;

    float *px,*pgx0,*pcx0,*poutT,*pout2,*pTg0,*pTg1,*pTc0,*pTc1;
    cudaGetSymbolAddress((void**)&px,    g_x);
    cudaGetSymbolAddress((void**)&pgx0,  g_gx0);
    cudaGetSymbolAddress((void**)&pcx0,  g_cx0);
    cudaGetSymbolAddress((void**)&poutT, g_outT);
    cudaGetSymbolAddress((void**)&pout2, g_out2);
    cudaGetSymbolAddress((void**)&pTg0,  g_Tg0);
    cudaGetSymbolAddress((void**)&pTg1,  g_Tg1);
    cudaGetSymbolAddress((void**)&pTc0,  g_Tc0);
    cudaGetSymbolAddress((void**)&pTc1,  g_Tc1);

    static bool attr_set = false;
    if (!attr_set){
        cudaFuncSetAttribute(rnn_persist, cudaFuncAttributeMaxDynamicSharedMemorySize, SMF*4);
        attr_set = true;
    }

    // weight transposes -> [n][k]
    tr_w<<<dim3(32,64), dim3(32,8)>>>(Wg0, 1024, H2, pTg0, H);
    tr_w<<<dim3(64,64), dim3(32,8)>>>(Wg1, 0,    H2, pTg1, H2);
    tr_w<<<dim3(32,32), dim3(32,8)>>>(Wc0, 1024, H,  pTc0, H);
    tr_w<<<dim3(64,32), dim3(32,8)>>>(Wc1, 0,    H,  pTc1, H2);

    embed_k<<<MROWS, 256>>>(idx, emb, px);

    // layer-0 x-projections -> [t][m][n]
    gemm_big<false,true><<<dim3(H2/64, MROWS/128), 256>>>(px, Wg0, nullptr, pgx0, MROWS, H2, H, H2);
    gemm_big<false,true><<<dim3(H/64,  MROWS/128), 256>>>(px, Wc0, nullptr, pcx0, MROWS, H, H, H);

    // pipelined recurrence
    rnn_persist<<<NB, NTHR, SMF*4>>>(bg0, bc0, bg1, bc1);

    // reorder + tied-softmax logits
    copy_out<<<MROWS, 256>>>(poutT, pout2);
    gemm_big<true,false><<<dim3((VOCAB+63)/64, MROWS/128), 256>>>(pout2, emb, smb, out, MROWS, VOCAB, H, H);
}

// round 7
// speedup vs baseline: 1.7646x; 1.0146x over previous
#include <cuda_runtime.h>
#include <math.h>
typedef unsigned long long ull;

#define VOCAB 10000
#define H 1024
#define H2 2048
#define BB 32
#define TT 128
#define MROWS (BB*TT)
#define NB 128
#define NTHR 512

// dynamic smem float offsets
#define OA    0        // A / A0: 2 x 8320
#define OA1   16640    // A1 (phase B): 2 x 8320
#define OWW   33280    // W: 2 x 8320 (A) / 2 x 4160 (B)
#define ORED  49920    // 4096
#define SMF   54016    // 216064 bytes

// ---------------- device scratch ----------------
__device__ __align__(16) float g_x[MROWS*H];
__device__ __align__(16) float g_gx0[(size_t)TT*BB*H2];  // [t][m][n]
__device__ __align__(16) float g_cx0[(size_t)TT*BB*H];   // [t][m][n]
__device__ __align__(16) float g_outT[(size_t)TT*BB*H];  // [t][m][n]
__device__ __align__(16) float g_out2[(size_t)MROWS*H];  // [m*T+t][n]
__device__ __align__(16) float g_h0m[2][BB*H];           // [m][n] ping-pong
__device__ __align__(16) float g_h1m[BB*H];
__device__ __align__(16) float g_rh0m[BB*H];
__device__ __align__(16) float g_rh1m[BB*H];
__device__ __align__(16) float g_u0m[BB*H];
__device__ __align__(16) float g_u1m[BB*H];
__device__ __align__(16) float g_Tg0[(size_t)H2*H];      // [n][k] = Wg0[1024+k][n]
__device__ __align__(16) float g_Tg1[(size_t)H2*H2];     // [n][k] = Wg1[k][n]
__device__ __align__(16) float g_Tc0[(size_t)H*H];       // [n][k] = Wc0[1024+k][n]
__device__ __align__(16) float g_Tc1[(size_t)H*H2];      // [n][k] = Wc1[k][n]
__device__ volatile unsigned g_cnt;
__device__ volatile unsigned g_gen;

// ---------------- helpers ----------------
__device__ __forceinline__ ull pdup(float x){ ull r; asm("mov.b64 %0,{%1,%1};":"=l"(r):"f"(x)); return r; }
__device__ __forceinline__ ull f2fma(ull a,ull x,ull y){ ull d; asm("fma.rn.f32x2 %0,%1,%2,%3;":"=l"(d):"l"(x),"l"(y),"l"(a)); return d; }
__device__ __forceinline__ float plo(ull v){ return __uint_as_float((unsigned)v); }
__device__ __forceinline__ float phi(ull v){ return __uint_as_float((unsigned)(v>>32)); }
__device__ __forceinline__ float sigf(float x){ return __fdividef(1.f, 1.f+__expf(-x)); }
__device__ __forceinline__ float tanhx(float x){ return 1.f-__fdividef(2.f, __expf(2.f*x)+1.f); }

__device__ __forceinline__ void cp16(float* d, const float* s){
    unsigned ds = (unsigned)__cvta_generic_to_shared(d);
    asm volatile("cp.async.cg.shared.global [%0], [%1], 16;" :: "r"(ds), "l"(s) : "memory");
}
#define CP_COMMIT asm volatile("cp.async.commit_group;" ::: "memory")
#define CP_WAIT1  asm volatile("cp.async.wait_group 1;" ::: "memory")
#define CP_WAIT0  asm volatile("cp.async.wait_group 0;" ::: "memory")

__device__ __forceinline__ void gsync(){
    __threadfence();
    __syncthreads();
    if (threadIdx.x == 0){
        unsigned gen = g_gen;
        unsigned old = atomicAdd((unsigned*)&g_cnt, 1u);
        if (old == NB-1){ g_cnt = 0; __threadfence(); g_gen = gen+1; }
        else { while (g_gen == gen) { } }
    }
    __syncthreads();
}

// ---------------- utility kernels ----------------
__global__ void embed_k(const int* __restrict__ idx, const float* __restrict__ emb,
                        float* __restrict__ x){
    int row = blockIdx.x, tid = threadIdx.x;
    ((float4*)(x + (size_t)row*H))[tid] = ((const float4*)(emb + (size_t)idx[row]*H))[tid];
}

__global__ void tr_w(const float* __restrict__ src, int srow0, int ld,
                     float* __restrict__ dst, int ldd){
    __shared__ float s[32][33];
    int kb = blockIdx.x*32, nb = blockIdx.y*32;
    int tx = threadIdx.x, ty = threadIdx.y;
#pragma unroll
    for (int i=0;i<32;i+=8) s[ty+i][tx] = src[(size_t)(srow0+kb+ty+i)*ld + nb+tx];
    __syncthreads();
#pragma unroll
    for (int i=0;i<32;i+=8) dst[(size_t)(nb+ty+i)*ldd + kb+tx] = s[tx][ty+i];
}

__global__ void copy_out(const float* __restrict__ outT, float* __restrict__ out2){
    int r = blockIdx.x;                   // m*128 + t
    int m = r>>7, t = r&127;
    ((float4*)(out2 + (size_t)r*H))[threadIdx.x] =
        ((const float4*)(outT + ((size_t)t*BB + m)*H))[threadIdx.x];
}

// ---------------- big GEMM (f32x2) ----------------
template<bool BT, bool GRUL>
__global__ void gemm_big(const float* __restrict__ A, const float* __restrict__ Bm,
                         const float* __restrict__ bias, float* __restrict__ C,
                         int M, int N, int K, int ldb)
{
    __shared__ __align__(16) float As[16][132];
    __shared__ __align__(16) float Bs[16][68];
    int m0 = blockIdx.y*128, n0 = blockIdx.x*64, tid = threadIdx.x;
    int mm0 = (tid>>4)*8, nn0 = (tid&15)*4;
    ull acc2[4][4];
#pragma unroll
    for (int p=0;p<4;p++)
#pragma unroll
        for (int c2=0;c2<4;c2++) acc2[p][c2]=0ull;

    for (int k0=0;k0<K;k0+=16){
#pragma unroll
        for (int i=0;i<2;i++){
            int f = tid + i*256, am = f>>2, kq = f&3;
            float4 v = *(const float4*)(A + (size_t)(m0+am)*K + k0 + kq*4);
            As[kq*4+0][am]=v.x; As[kq*4+1][am]=v.y; As[kq*4+2][am]=v.z; As[kq*4+3][am]=v.w;
        }
        if (!BT){
            int brow = tid>>4, n = n0 + (tid&15)*4;
            float4 v;
            if (n+3 < N) v = *(const float4*)(Bm + (size_t)(k0+brow)*ldb + n);
            else {
                v.x=(n+0<N)?Bm[(size_t)(k0+brow)*ldb+n+0]:0.f;
                v.y=(n+1<N)?Bm[(size_t)(k0+brow)*ldb+n+1]:0.f;
                v.z=(n+2<N)?Bm[(size_t)(k0+brow)*ldb+n+2]:0.f;
                v.w=(n+3<N)?Bm[(size_t)(k0+brow)*ldb+n+3]:0.f;
            }
            *(float4*)&Bs[brow][(tid&15)*4] = v;
        } else {
            int nrow = tid>>2, kq = tid&3, n = n0+nrow;
            float4 v = make_float4(0.f,0.f,0.f,0.f);
            if (n < N) v = *(const float4*)(Bm + (size_t)n*ldb + k0 + kq*4);
            Bs[kq*4+0][nrow]=v.x; Bs[kq*4+1][nrow]=v.y; Bs[kq*4+2][nrow]=v.z; Bs[kq*4+3][nrow]=v.w;
        }
        __syncthreads();
#pragma unroll
        for (int kk=0;kk<16;kk++){
            ulonglong2 a01 = *(const ulonglong2*)&As[kk][mm0];
            ulonglong2 a23 = *(const ulonglong2*)&As[kk][mm0+4];
            float4 tb = *(const float4*)&Bs[kk][nn0];
            ull b0=pdup(tb.x), b1=pdup(tb.y), b2=pdup(tb.z), b3=pdup(tb.w);
            acc2[0][0]=f2fma(acc2[0][0],a01.x,b0); acc2[0][1]=f2fma(acc2[0][1],a01.x,b1);
            acc2[0][2]=f2fma(acc2[0][2],a01.x,b2); acc2[0][3]=f2fma(acc2[0][3],a01.x,b3);
            acc2[1][0]=f2fma(acc2[1][0],a01.y,b0); acc2[1][1]=f2fma(acc2[1][1],a01.y,b1);
            acc2[1][2]=f2fma(acc2[1][2],a01.y,b2); acc2[1][3]=f2fma(acc2[1][3],a01.y,b3);
            acc2[2][0]=f2fma(acc2[2][0],a23.x,b0); acc2[2][1]=f2fma(acc2[2][1],a23.x,b1);
            acc2[2][2]=f2fma(acc2[2][2],a23.x,b2); acc2[2][3]=f2fma(acc2[2][3],a23.x,b3);
            acc2[3][0]=f2fma(acc2[3][0],a23.y,b0); acc2[3][1]=f2fma(acc2[3][1],a23.y,b1);
            acc2[3][2]=f2fma(acc2[3][2],a23.y,b2); acc2[3][3]=f2fma(acc2[3][3],a23.y,b3);
        }
        __syncthreads();
    }
#pragma unroll
    for (int p=0;p<4;p++)
#pragma unroll
        for (int c2=0;c2<4;c2++){
            int n = n0+nn0+c2;
            if (n < N){
                float v0 = plo(acc2[p][c2]), v1 = phi(acc2[p][c2]);
                if (bias){ v0 += bias[n]; v1 += bias[n]; }
                int r0 = m0+mm0+2*p, r1 = r0+1;
                if (GRUL){
                    C[((size_t)((r0&127)*BB + (r0>>7)))*N + n] = v0;
                    C[((size_t)((r1&127)*BB + (r1>>7)))*N + n] = v1;
                } else {
                    C[(size_t)r0*N + n] = v0;
                    C[(size_t)r1*N + n] = v1;
                }
            }
        }
}

// ---------------- persistent recurrence (broadcast-W MAC) ----------------
__global__ void __launch_bounds__(NTHR, 1)
rnn_persist(const float* __restrict__ bg0, const float* __restrict__ bc0,
            const float* __restrict__ bg1, const float* __restrict__ bc1)
{
    extern __shared__ __align__(16) float sm[];
    const int tid = threadIdx.x, c = blockIdx.x;
    const int lane = tid & 31, w = tid >> 5;

    for (int i = c*NTHR+tid; i < BB*H; i += NB*NTHR){ g_h0m[0][i]=0.f; g_h1m[i]=0.f; }
    gsync();

    const int tnA = w & 3, ksA = w >> 2;   // 4 tiles x 4 k-splits
    const bool aL0 = tnA < 2;
    const int tnB = w & 1, ksB = w >> 1;   // 2 tiles x 8 k-splits
    const bool bL0 = (tnB == 0);

    float* red = sm + ORED;
    int cur = 0;

    for (int t = 0; t <= TT; t++){
        const bool do0 = (t < TT), do1 = (t > 0);
        const float* __restrict__ h0c = g_h0m[cur];
        float* __restrict__ h0p = g_h0m[cur^1];
        const int nc = do1 ? 8 : 4;

        // ================= PHASE A: gates =================
        {
            auto stage = [&](int kc){
                float* Ab = sm + OA + (kc&1)*8320;
                const float* src = (kc<4) ? h0c + kc*256 : g_h1m + (kc-4)*256;
                #pragma unroll
                for (int u=0;u<4;u++){ int f = tid+u*NTHR; int m = f>>6, kq = f&63;
                    cp16(Ab + m*260 + kq*4, src + m*H + kq*4); }
                float* Wb = sm + OWW + (kc&1)*8320;
                if (kc < 4){
                    #pragma unroll
                    for (int u=0;u<4;u++){ int f = tid+u*NTHR; int r = f>>6, kq = f&63;
                        const float* ws = (r<16) ? g_Tg0 + (size_t)(c*16+r)*H + kc*256
                                                 : g_Tg1 + (size_t)(c*16+r-16)*H2 + kc*256;
                        cp16(Wb + r*260 + kq*4, ws + kq*4); }
                } else {
                    #pragma unroll
                    for (int u=0;u<2;u++){ int f = tid+u*NTHR; int r = 16+(f>>6), kq = f&63;
                        cp16(Wb + r*260 + kq*4,
                             g_Tg1 + (size_t)(c*16+r-16)*H2 + kc*256 + kq*4); }
                }
            };
            stage(0); CP_COMMIT;
            ull acc[8];
            #pragma unroll
            for (int j=0;j<8;j++) acc[j] = 0ull;

            for (int kc=0;kc<nc;kc++){
                if (kc+1 < nc){ stage(kc+1); CP_COMMIT; CP_WAIT1; } else CP_WAIT0;
                __syncthreads();
                const bool act = aL0 ? (do0 && kc < 4) : do1;
                if (act){
                    const float* Ap = sm + OA + (kc&1)*8320 + lane*260 + ksA*64;
                    const float* Wp = sm + OWW + (kc&1)*8320 + (tnA*8)*260 + ksA*64;
                    #pragma unroll
                    for (int i=0;i<16;i++){
                        ulonglong2 a = *(const ulonglong2*)(Ap + i*4);
                        #pragma unroll
                        for (int j=0;j<8;j++){
                            ulonglong2 wv = *(const ulonglong2*)(Wp + j*260 + i*4);
                            acc[j] = f2fma(f2fma(acc[j], a.x, wv.x), a.y, wv.y);
                        }
                    }
                }
                __syncthreads();
            }
            #pragma unroll
            for (int j=0;j<8;j++)
                red[((tnA*8+j)*4 + ksA)*32 + lane] = plo(acc[j]) + phi(acc[j]);
            __syncthreads();
            #pragma unroll
            for (int q=0;q<2;q++){
                int o = tid*2+q, col = o>>5, m = o&31;
                const float* rp = red + col*128 + m;
                float s = rp[0] + rp[32] + rp[64] + rp[96];
                if (col < 16){
                    if (do0){
                        int n = c*16 + col;
                        s += g_gx0[((size_t)t*BB+m)*H2 + n] + bg0[n];
                        float g = sigf(s);
                        if (n < H) g_rh0m[m*H+n] = g * h0c[m*H+n];
                        else       g_u0m[m*H + n-H] = g;
                    }
                } else {
                    if (do1){
                        int n = c*16 + col - 16;
                        s += bg1[n];
                        float g = sigf(s);
                        if (n < H) g_rh1m[m*H+n] = g * g_h1m[m*H+n];
                        else       g_u1m[m*H + n-H] = g;
                    }
                }
            }
        }
        gsync();

        // ================= PHASE B: candidates + update =================
        {
            auto stage = [&](int kc){
                if (kc < 4){
                    float* A0b = sm + OA + (kc&1)*8320;
                    const float* s0 = g_rh0m + kc*256;
                    #pragma unroll
                    for (int u=0;u<4;u++){ int f = tid+u*NTHR; int m = f>>6, kq = f&63;
                        cp16(A0b + m*260 + kq*4, s0 + m*H + kq*4); }
                }
                float* A1b = sm + OA1 + (kc&1)*8320;
                const float* s1 = (kc<4) ? h0c + kc*256 : g_rh1m + (kc-4)*256;
                #pragma unroll
                for (int u=0;u<4;u++){ int f = tid+u*NTHR; int m = f>>6, kq = f&63;
                    cp16(A1b + m*260 + kq*4, s1 + m*H + kq*4); }
                float* Wb = sm + OWW + (kc&1)*4160;
                if (kc < 4){
                    #pragma unroll
                    for (int u=0;u<2;u++){ int f = tid+u*NTHR; int r = f>>6, kq = f&63;
                        const float* ws = (r<8) ? g_Tc0 + (size_t)(c*8+r)*H + kc*256
                                                : g_Tc1 + (size_t)(c*8+r-8)*H2 + kc*256;
                        cp16(Wb + r*260 + kq*4, ws + kq*4); }
                } else {
                    int r = 8+(tid>>6), kq = tid&63;
                    cp16(Wb + r*260 + kq*4,
                         g_Tc1 + (size_t)(c*8+r-8)*H2 + kc*256 + kq*4);
                }
            };
            stage(0); CP_COMMIT;
            ull acc[8];
            #pragma unroll
            for (int j=0;j<8;j++) acc[j] = 0ull;

            for (int kc=0;kc<nc;kc++){
                if (kc+1 < nc){ stage(kc+1); CP_COMMIT; CP_WAIT1; } else CP_WAIT0;
                __syncthreads();
                const bool act = bL0 ? (do0 && kc < 4) : do1;
                if (act){
                    const float* Ap = sm + (bL0 ? OA : OA1) + (kc&1)*8320 + lane*260 + ksB*32;
                    const float* Wp = sm + OWW + (kc&1)*4160 + (tnB*8)*260 + ksB*32;
                    #pragma unroll
                    for (int i=0;i<8;i++){
                        ulonglong2 a = *(const ulonglong2*)(Ap + i*4);
                        #pragma unroll
                        for (int j=0;j<8;j++){
                            ulonglong2 wv = *(const ulonglong2*)(Wp + j*260 + i*4);
                            acc[j] = f2fma(f2fma(acc[j], a.x, wv.x), a.y, wv.y);
                        }
                    }
                }
                __syncthreads();
            }
            #pragma unroll
            for (int j=0;j<8;j++)
                red[((tnB*8+j)*8 + ksB)*32 + lane] = plo(acc[j]) + phi(acc[j]);
            __syncthreads();
            {
                int col = tid>>5, m = tid&31;
                const float* rp = red + col*256 + m;
                float s = rp[0]+rp[32]+rp[64]+rp[96]+rp[128]+rp[160]+rp[192]+rp[224];
                if (col < 8){
                    if (do0){
                        int n = c*8 + col;
                        s += g_cx0[((size_t)t*BB+m)*H + n] + bc0[n];
                        float cc = tanhx(s);
                        float u = g_u0m[m*H+n];
                        h0p[m*H+n] = u*h0c[m*H+n] + (1.f-u)*cc;
                    }
                } else {
                    if (do1){
                        int n = c*8 + col - 8;
                        s += bc1[n];
                        float cc = tanhx(s);
                        float u = g_u1m[m*H+n];
                        float hn = u*g_h1m[m*H+n] + (1.f-u)*cc;
                        g_h1m[m*H+n] = hn;
                        g_outT[((size_t)(t-1)*BB+m)*H + n] = hn;
                    }
                }
            }
        }
        cur ^= 1;
        gsync();
    }
}

// ---------------- launch ----------------
extern "C" void kernel_launch(void* const* d_in, const int* in_sizes, int n_in,
                              void* d_out, int out_size)
{
    const int*   idx = (const int*)  d_in[0];
    const float* emb = (const float*)d_in[1];
    const float* Wg0 = (const float*)d_in[2];
    const float* bg0 = (const float*)d_in[3];
    const float* Wc0 = (const float*)d_in[4];
    const float* bc0 = (const float*)d_in[5];
    const float* Wg1 = (const float*)d_in[6];
    const float* bg1 = (const float*)d_in[7];
    const float* Wc1 = (const float*)d_in[8];
    const float* bc1 = (const float*)d_in[9];
    const float* smb = (const float*)d_in[10];
    float* out = (float*)d_out;

    float *px,*pgx0,*pcx0,*poutT,*pout2,*pTg0,*pTg1,*pTc0,*pTc1;
    cudaGetSymbolAddress((void**)&px,    g_x);
    cudaGetSymbolAddress((void**)&pgx0,  g_gx0);
    cudaGetSymbolAddress((void**)&pcx0,  g_cx0);
    cudaGetSymbolAddress((void**)&poutT, g_outT);
    cudaGetSymbolAddress((void**)&pout2, g_out2);
    cudaGetSymbolAddress((void**)&pTg0,  g_Tg0);
    cudaGetSymbolAddress((void**)&pTg1,  g_Tg1);
    cudaGetSymbolAddress((void**)&pTc0,  g_Tc0);
    cudaGetSymbolAddress((void**)&pTc1,  g_Tc1);

    static bool attr_set = false;
    if (!attr_set){
        cudaFuncSetAttribute(rnn_persist, cudaFuncAttributeMaxDynamicSharedMemorySize, SMF*4);
        attr_set = true;
    }

    // weight transposes -> [n][k]
    tr_w<<<dim3(32,64), dim3(32,8)>>>(Wg0, 1024, H2, pTg0, H);
    tr_w<<<dim3(64,64), dim3(32,8)>>>(Wg1, 0,    H2, pTg1, H2);
    tr_w<<<dim3(32,32), dim3(32,8)>>>(Wc0, 1024, H,  pTc0, H);
    tr_w<<<dim3(64,32), dim3(32,8)>>>(Wc1, 0,    H,  pTc1, H2);

    embed_k<<<MROWS, 256>>>(idx, emb, px);

    // layer-0 x-projections -> [t][m][n]
    gemm_big<false,true><<<dim3(H2/64, MROWS/128), 256>>>(px, Wg0, nullptr, pgx0, MROWS, H2, H, H2);
    gemm_big<false,true><<<dim3(H/64,  MROWS/128), 256>>>(px, Wc0, nullptr, pcx0, MROWS, H, H, H);

    // pipelined recurrence
    rnn_persist<<<NB, NTHR, SMF*4>>>(bg0, bc0, bg1, bc1);

    // reorder + tied-softmax logits
    copy_out<<<MROWS, 256>>>(poutT, pout2);
    gemm_big<true,false><<<dim3((VOCAB+63)/64, MROWS/128), 256>>>(pout2, emb, smb, out, MROWS, VOCAB, H, H);
}

// round 9
// speedup vs baseline: 2.0575x; 1.1660x over previous
#include <cuda_runtime.h>
#include <cuda_bf16.h>
#include <math.h>
typedef unsigned long long ull;
typedef __nv_bfloat16 bf16;

#define VOCAB 10000
#define VPAD  10048
#define H 1024
#define H2 2048
#define BB 32
#define TT 128
#define MROWS (BB*TT)
#define NB 128
#define NTHR 512

// recurrence smem float offsets (r7, unchanged)
#define OA    0
#define OA1   16640
#define OWW   33280
#define ORED  49920
#define SMF   54016

// hgemm smem (bytes)
#define HA_L 18432
#define HB_H 36864
#define HB_L 46080
#define HBUF 55296
#define HSM  (2*HBUF)

// ---------------- device scratch ----------------
__device__ __align__(16) float g_gx0[(size_t)TT*BB*H2];
__device__ __align__(16) float g_cx0[(size_t)TT*BB*H];
__device__ __align__(16) float g_outT[(size_t)TT*BB*H];
__device__ __align__(16) float g_h0m[2][BB*H];
__device__ __align__(16) float g_h1m[BB*H];
__device__ __align__(16) float g_rh0m[BB*H];
__device__ __align__(16) float g_rh1m[BB*H];
__device__ __align__(16) float g_u0m[BB*H];
__device__ __align__(16) float g_u1m[BB*H];
__device__ __align__(16) float g_Tg0[(size_t)H2*H];
__device__ __align__(16) float g_Tg1[(size_t)H2*H2];
__device__ __align__(16) float g_Tc0[(size_t)H*H];
__device__ __align__(16) float g_Tc1[(size_t)H*H2];
__device__ __align__(16) bf16 g_xh[(size_t)MROWS*H], g_xl[(size_t)MROWS*H];
__device__ __align__(16) bf16 g_oh[(size_t)MROWS*H], g_ol[(size_t)MROWS*H];
__device__ __align__(16) bf16 g_wgh[(size_t)H2*H],  g_wgl[(size_t)H2*H];
__device__ __align__(16) bf16 g_wch[(size_t)H*H],   g_wcl[(size_t)H*H];
__device__ __align__(16) bf16 g_eh[(size_t)VPAD*H], g_el[(size_t)VPAD*H];
__device__ volatile unsigned g_cnt;
__device__ volatile unsigned g_gen;

// ---------------- helpers ----------------
__device__ __forceinline__ ull f2fma(ull a,ull x,ull y){ ull d; asm("fma.rn.f32x2 %0,%1,%2,%3;":"=l"(d):"l"(x),"l"(y),"l"(a)); return d; }
__device__ __forceinline__ float plo(ull v){ return __uint_as_float((unsigned)v); }
__device__ __forceinline__ float phi(ull v){ return __uint_as_float((unsigned)(v>>32)); }
__device__ __forceinline__ float sigf(float x){ return __fdividef(1.f, 1.f+__expf(-x)); }
__device__ __forceinline__ float tanhx(float x){ return 1.f-__fdividef(2.f, __expf(2.f*x)+1.f); }

__device__ __forceinline__ void cp16(void* d, const void* s){
    unsigned ds = (unsigned)__cvta_generic_to_shared(d);
    asm volatile("cp.async.cg.shared.global [%0], [%1], 16;" :: "r"(ds), "l"(s) : "memory");
}
#define CP_COMMIT asm volatile("cp.async.commit_group;" ::: "memory")
#define CP_WAIT1  asm volatile("cp.async.wait_group 1;" ::: "memory")
#define CP_WAIT0  asm volatile("cp.async.wait_group 0;" ::: "memory")

__device__ __forceinline__ void gsync(){
    __threadfence();
    __syncthreads();
    if (threadIdx.x == 0){
        unsigned gen = g_gen;
        unsigned old = atomicAdd((unsigned*)&g_cnt, 1u);
        if (old == NB-1){ g_cnt = 0; __threadfence(); g_gen = gen+1; }
        else { while (g_gen == gen) { } }
    }
    __syncthreads();
}

// ---------------- HMMA primitives (generic-target safe) ----------------
__device__ __forceinline__ void ldm4(unsigned& r0, unsigned& r1, unsigned& r2, unsigned& r3,
                                     unsigned addr){
    asm volatile("ldmatrix.sync.aligned.m8n8.x4.shared.b16 {%0,%1,%2,%3}, [%4];"
        : "=r"(r0), "=r"(r1), "=r"(r2), "=r"(r3) : "r"(addr));
}
__device__ __forceinline__ void mma16816(float* c, const unsigned* a, const unsigned* b){
    asm volatile("mma.sync.aligned.m16n8k16.row.col.f32.bf16.bf16.f32 "
        "{%0,%1,%2,%3},{%4,%5,%6,%7},{%8,%9},{%0,%1,%2,%3};"
        : "+f"(c[0]), "+f"(c[1]), "+f"(c[2]), "+f"(c[3])
        : "r"(a[0]), "r"(a[1]), "r"(a[2]), "r"(a[3]), "r"(b[0]), "r"(b[1]));
}

// ---------------- utility kernels ----------------
__global__ void embed2(const int* __restrict__ idx, const float* __restrict__ emb,
                       bf16* __restrict__ xh, bf16* __restrict__ xl){
    int row = blockIdx.x, tid = threadIdx.x;
    float4 v = ((const float4*)(emb + (size_t)idx[row]*H))[tid];
    float a[4] = {v.x,v.y,v.z,v.w};
    size_t o = (size_t)row*H + tid*4;
#pragma unroll
    for (int j=0;j<4;j++){
        bf16 h = __float2bfloat16(a[j]);
        xh[o+j] = h;
        xl[o+j] = __float2bfloat16(a[j] - __bfloat162float(h));
    }
}

__global__ void econv(const float* __restrict__ emb, bf16* __restrict__ eh, bf16* __restrict__ el){
    int row = blockIdx.x, tid = threadIdx.x;
    size_t o = (size_t)row*H + tid*4;
    if (row < VOCAB){
        float4 v = ((const float4*)(emb + (size_t)row*H))[tid];
        float a[4] = {v.x,v.y,v.z,v.w};
#pragma unroll
        for (int j=0;j<4;j++){
            bf16 h = __float2bfloat16(a[j]);
            eh[o+j] = h;
            el[o+j] = __float2bfloat16(a[j] - __bfloat162float(h));
        }
    } else {
#pragma unroll
        for (int j=0;j<4;j++){ eh[o+j] = __float2bfloat16(0.f); el[o+j] = __float2bfloat16(0.f); }
    }
}

__global__ void outconv(const float* __restrict__ outT, bf16* __restrict__ oh, bf16* __restrict__ ol){
    int r = blockIdx.x, tid = threadIdx.x;
    int m = r>>7, t = r&127;
    float4 v = ((const float4*)(outT + ((size_t)t*BB + m)*H))[tid];
    float a[4] = {v.x,v.y,v.z,v.w};
    size_t o = (size_t)r*H + tid*4;
#pragma unroll
    for (int j=0;j<4;j++){
        bf16 h = __float2bfloat16(a[j]);
        oh[o+j] = h;
        ol[o+j] = __float2bfloat16(a[j] - __bfloat162float(h));
    }
}

__global__ void tr_w(const float* __restrict__ src, int srow0, int ld,
                     float* __restrict__ dst, int ldd){
    __shared__ float s[32][33];
    int kb = blockIdx.x*32, nb = blockIdx.y*32;
    int tx = threadIdx.x, ty = threadIdx.y;
#pragma unroll
    for (int i=0;i<32;i+=8) s[ty+i][tx] = src[(size_t)(srow0+kb+ty+i)*ld + nb+tx];
    __syncthreads();
#pragma unroll
    for (int i=0;i<32;i+=8) dst[(size_t)(nb+ty+i)*ldd + kb+tx] = s[tx][ty+i];
}

__global__ void tr_split(const float* __restrict__ src, int ld,
                         bf16* __restrict__ hi, bf16* __restrict__ lo){
    __shared__ float s[32][33];
    int kb = blockIdx.x*32, nb = blockIdx.y*32;
    int tx = threadIdx.x, ty = threadIdx.y;
#pragma unroll
    for (int i=0;i<32;i+=8) s[ty+i][tx] = src[(size_t)(kb+ty+i)*ld + nb+tx];
    __syncthreads();
#pragma unroll
    for (int i=0;i<32;i+=8){
        float v = s[tx][ty+i];
        bf16 h = __float2bfloat16(v);
        size_t o = (size_t)(nb+ty+i)*H + kb+tx;
        hi[o] = h;
        lo[o] = __float2bfloat16(v - __bfloat162float(h));
    }
}

// ---------------- HMMA bf16-split GEMM ----------------
// C[M tiles of 128][N tiles of 64] = (Ah+Al)[m][k] . (Bh+Bl)[n][k], K=1024.
template<bool GRUL>
__global__ void __launch_bounds__(256, 1)
hgemm(const bf16* __restrict__ Ah, const bf16* __restrict__ Al,
      const bf16* __restrict__ Bh, const bf16* __restrict__ Bl,
      const float* __restrict__ bias, float* __restrict__ C, int N)
{
    extern __shared__ __align__(16) char smc[];
    const int tid = threadIdx.x, wid = tid>>5, lane = tid&31;
    const int n0 = blockIdx.x*64, m0 = blockIdx.y*128;
    const int wm = wid&3, wn = wid>>2;
    unsigned sb = (unsigned)__cvta_generic_to_shared(smc);

    auto stage = [&](int kc){
        char* base = smc + (kc&1)*HBUF;
#pragma unroll
        for (int u=0;u<8;u++){
            int e = tid + u*256;
            int pl = e>>10, i = e&1023, row = i>>3, g = i&7;
            const bf16* src = (pl?Al:Ah) + (size_t)(m0+row)*H + kc*64 + g*8;
            cp16(base + (pl?HA_L:0) + row*144 + g*16, src);
        }
#pragma unroll
        for (int u=0;u<4;u++){
            int e = tid + u*256;
            int pl = e>>9, i = e&511, row = i>>3, g = i&7;
            const bf16* src = (pl?Bl:Bh) + (size_t)(n0+row)*H + kc*64 + g*8;
            cp16(base + (pl?HB_L:HB_H) + row*144 + g*16, src);
        }
    };

    float cc[2][4][4];
#pragma unroll
    for (int a=0;a<2;a++)
#pragma unroll
        for (int b=0;b<4;b++)
#pragma unroll
            for (int q=0;q<4;q++) cc[a][b][q] = 0.f;

    stage(0); CP_COMMIT;
    for (int kc=0;kc<16;kc++){
        if (kc < 15){ stage(kc+1); CP_COMMIT; CP_WAIT1; } else CP_WAIT0;
        __syncthreads();
        unsigned bufb = sb + (kc&1)*HBUF;
        // A frag base: row = wm*32 + (lane&15), k-half = (lane>>4)&1
        unsigned aB = bufb + (wm*32 + (lane&15))*144 + ((lane>>4)&1)*16;
        // B frag base: n = wn*32 + (lane&7) + 8*((lane>>4)&1), k-half = (lane>>3)&1
        unsigned bB = bufb + HB_H + (wn*32 + (lane&7) + ((lane>>4)&1)*8)*144 + ((lane>>3)&1)*16;
#pragma unroll
        for (int ks=0;ks<4;ks++){
            unsigned ah[8], al[8], bh[8], bl[8];
            ldm4(ah[0],ah[1],ah[2],ah[3], aB + ks*32);
            ldm4(ah[4],ah[5],ah[6],ah[7], aB + 16*144 + ks*32);
            ldm4(al[0],al[1],al[2],al[3], aB + HA_L + ks*32);
            ldm4(al[4],al[5],al[6],al[7], aB + HA_L + 16*144 + ks*32);
            ldm4(bh[0],bh[1],bh[2],bh[3], bB + ks*32);
            ldm4(bh[4],bh[5],bh[6],bh[7], bB + 16*144 + ks*32);
            ldm4(bl[0],bl[1],bl[2],bl[3], bB + (HB_L-HB_H) + ks*32);
            ldm4(bl[4],bl[5],bl[6],bl[7], bB + (HB_L-HB_H) + 16*144 + ks*32);
#pragma unroll
            for (int fm=0;fm<2;fm++)
#pragma unroll
                for (int fn=0;fn<4;fn++){
                    mma16816(cc[fm][fn], ah+fm*4, bh+fn*2);
                    mma16816(cc[fm][fn], ah+fm*4, bl+fn*2);
                    mma16816(cc[fm][fn], al+fm*4, bh+fn*2);
                }
        }
        __syncthreads();
    }

    // epilogue
    const int rb = lane>>2, cb = (lane&3)*2;
#pragma unroll
    for (int fm=0;fm<2;fm++){
#pragma unroll
        for (int half=0;half<2;half++){
            int r = m0 + wm*32 + fm*16 + rb + half*8;
            int r2 = GRUL ? ((r & 127)*BB + (r >> 7)) : r;
            float* crow = C + (size_t)r2*N;
#pragma unroll
            for (int fn=0;fn<4;fn++){
                int n = n0 + wn*32 + fn*8 + cb;
                if (n < N){
                    float2 v;
                    v.x = cc[fm][fn][half*2+0];
                    v.y = cc[fm][fn][half*2+1];
                    if (bias){
                        float2 b = *(const float2*)(bias + n);
                        v.x += b.x; v.y += b.y;
                    }
                    *(float2*)(crow + n) = v;
                }
            }
        }
    }
}

// ---------------- persistent recurrence (r7, unchanged) ----------------
__global__ void __launch_bounds__(NTHR, 1)
rnn_persist(const float* __restrict__ bg0, const float* __restrict__ bc0,
            const float* __restrict__ bg1, const float* __restrict__ bc1)
{
    extern __shared__ __align__(16) float sm[];
    const int tid = threadIdx.x, c = blockIdx.x;
    const int lane = tid & 31, w = tid >> 5;

    for (int i = c*NTHR+tid; i < BB*H; i += NB*NTHR){ g_h0m[0][i]=0.f; g_h1m[i]=0.f; }
    gsync();

    const int tnA = w & 3, ksA = w >> 2;
    const bool aL0 = tnA < 2;
    const int tnB = w & 1, ksB = w >> 1;
    const bool bL0 = (tnB == 0);

    float* red = sm + ORED;
    int cur = 0;

    for (int t = 0; t <= TT; t++){
        const bool do0 = (t < TT), do1 = (t > 0);
        const float* __restrict__ h0c = g_h0m[cur];
        float* __restrict__ h0p = g_h0m[cur^1];
        const int nc = do1 ? 8 : 4;

        // PHASE A: gates
        {
            auto stage = [&](int kc){
                float* Ab = sm + OA + (kc&1)*8320;
                const float* src = (kc<4) ? h0c + kc*256 : g_h1m + (kc-4)*256;
                #pragma unroll
                for (int u=0;u<4;u++){ int f = tid+u*NTHR; int m = f>>6, kq = f&63;
                    cp16(Ab + m*260 + kq*4, src + m*H + kq*4); }
                float* Wb = sm + OWW + (kc&1)*8320;
                if (kc < 4){
                    #pragma unroll
                    for (int u=0;u<4;u++){ int f = tid+u*NTHR; int r = f>>6, kq = f&63;
                        const float* ws = (r<16) ? g_Tg0 + (size_t)(c*16+r)*H + kc*256
                                                 : g_Tg1 + (size_t)(c*16+r-16)*H2 + kc*256;
                        cp16(Wb + r*260 + kq*4, ws + kq*4); }
                } else {
                    #pragma unroll
                    for (int u=0;u<2;u++){ int f = tid+u*NTHR; int r = 16+(f>>6), kq = f&63;
                        cp16(Wb + r*260 + kq*4,
                             g_Tg1 + (size_t)(c*16+r-16)*H2 + kc*256 + kq*4); }
                }
            };
            stage(0); CP_COMMIT;
            ull acc[8];
            #pragma unroll
            for (int j=0;j<8;j++) acc[j] = 0ull;
            for (int kc=0;kc<nc;kc++){
                if (kc+1 < nc){ stage(kc+1); CP_COMMIT; CP_WAIT1; } else CP_WAIT0;
                __syncthreads();
                const bool act = aL0 ? (do0 && kc < 4) : do1;
                if (act){
                    const float* Ap = sm + OA + (kc&1)*8320 + lane*260 + ksA*64;
                    const float* Wp = sm + OWW + (kc&1)*8320 + (tnA*8)*260 + ksA*64;
                    #pragma unroll
                    for (int i=0;i<16;i++){
                        ulonglong2 a = *(const ulonglong2*)(Ap + i*4);
                        #pragma unroll
                        for (int j=0;j<8;j++){
                            ulonglong2 wv = *(const ulonglong2*)(Wp + j*260 + i*4);
                            acc[j] = f2fma(f2fma(acc[j], a.x, wv.x), a.y, wv.y);
                        }
                    }
                }
                __syncthreads();
            }
            #pragma unroll
            for (int j=0;j<8;j++)
                red[((tnA*8+j)*4 + ksA)*32 + lane] = plo(acc[j]) + phi(acc[j]);
            __syncthreads();
            #pragma unroll
            for (int q=0;q<2;q++){
                int o = tid*2+q, col = o>>5, m = o&31;
                const float* rp = red + col*128 + m;
                float s = rp[0] + rp[32] + rp[64] + rp[96];
                if (col < 16){
                    if (do0){
                        int n = c*16 + col;
                        s += g_gx0[((size_t)t*BB+m)*H2 + n] + bg0[n];
                        float g = sigf(s);
                        if (n < H) g_rh0m[m*H+n] = g * h0c[m*H+n];
                        else       g_u0m[m*H + n-H] = g;
                    }
                } else {
                    if (do1){
                        int n = c*16 + col - 16;
                        s += bg1[n];
                        float g = sigf(s);
                        if (n < H) g_rh1m[m*H+n] = g * g_h1m[m*H+n];
                        else       g_u1m[m*H + n-H] = g;
                    }
                }
            }
        }
        gsync();

        // PHASE B: candidates + update
        {
            auto stage = [&](int kc){
                if (kc < 4){
                    float* A0b = sm + OA + (kc&1)*8320;
                    const float* s0 = g_rh0m + kc*256;
                    #pragma unroll
                    for (int u=0;u<4;u++){ int f = tid+u*NTHR; int m = f>>6, kq = f&63;
                        cp16(A0b + m*260 + kq*4, s0 + m*H + kq*4); }
                }
                float* A1b = sm + OA1 + (kc&1)*8320;
                const float* s1 = (kc<4) ? h0c + kc*256 : g_rh1m + (kc-4)*256;
                #pragma unroll
                for (int u=0;u<4;u++){ int f = tid+u*NTHR; int m = f>>6, kq = f&63;
                    cp16(A1b + m*260 + kq*4, s1 + m*H + kq*4); }
                float* Wb = sm + OWW + (kc&1)*4160;
                if (kc < 4){
                    #pragma unroll
                    for (int u=0;u<2;u++){ int f = tid+u*NTHR; int r = f>>6, kq = f&63;
                        const float* ws = (r<8) ? g_Tc0 + (size_t)(c*8+r)*H + kc*256
                                                : g_Tc1 + (size_t)(c*8+r-8)*H2 + kc*256;
                        cp16(Wb + r*260 + kq*4, ws + kq*4); }
                } else {
                    int r = 8+(tid>>6), kq = tid&63;
                    cp16(Wb + r*260 + kq*4,
                         g_Tc1 + (size_t)(c*8+r-8)*H2 + kc*256 + kq*4);
                }
            };
            stage(0); CP_COMMIT;
            ull acc[8];
            #pragma unroll
            for (int j=0;j<8;j++) acc[j] = 0ull;
            for (int kc=0;kc<nc;kc++){
                if (kc+1 < nc){ stage(kc+1); CP_COMMIT; CP_WAIT1; } else CP_WAIT0;
                __syncthreads();
                const bool act = bL0 ? (do0 && kc < 4) : do1;
                if (act){
                    const float* Ap = sm + (bL0 ? OA : OA1) + (kc&1)*8320 + lane*260 + ksB*32;
                    const float* Wp = sm + OWW + (kc&1)*4160 + (tnB*8)*260 + ksB*32;
                    #pragma unroll
                    for (int i=0;i<8;i++){
                        ulonglong2 a = *(const ulonglong2*)(Ap + i*4);
                        #pragma unroll
                        for (int j=0;j<8;j++){
                            ulonglong2 wv = *(const ulonglong2*)(Wp + j*260 + i*4);
                            acc[j] = f2fma(f2fma(acc[j], a.x, wv.x), a.y, wv.y);
                        }
                    }
                }
                __syncthreads();
            }
            #pragma unroll
            for (int j=0;j<8;j++)
                red[((tnB*8+j)*8 + ksB)*32 + lane] = plo(acc[j]) + phi(acc[j]);
            __syncthreads();
            {
                int col = tid>>5, m = tid&31;
                const float* rp = red + col*256 + m;
                float s = rp[0]+rp[32]+rp[64]+rp[96]+rp[128]+rp[160]+rp[192]+rp[224];
                if (col < 8){
                    if (do0){
                        int n = c*8 + col;
                        s += g_cx0[((size_t)t*BB+m)*H + n] + bc0[n];
                        float cc2 = tanhx(s);
                        float u = g_u0m[m*H+n];
                        h0p[m*H+n] = u*h0c[m*H+n] + (1.f-u)*cc2;
                    }
                } else {
                    if (do1){
                        int n = c*8 + col - 8;
                        s += bc1[n];
                        float cc2 = tanhx(s);
                        float u = g_u1m[m*H+n];
                        float hn = u*g_h1m[m*H+n] + (1.f-u)*cc2;
                        g_h1m[m*H+n] = hn;
                        g_outT[((size_t)(t-1)*BB+m)*H + n] = hn;
                    }
                }
            }
        }
        cur ^= 1;
        gsync();
    }
}

// ---------------- launch ----------------
extern "C" void kernel_launch(void* const* d_in, const int* in_sizes, int n_in,
                              void* d_out, int out_size)
{
    const int*   idx = (const int*)  d_in[0];
    const float* emb = (const float*)d_in[1];
    const float* Wg0 = (const float*)d_in[2];
    const float* bg0 = (const float*)d_in[3];
    const float* Wc0 = (const float*)d_in[4];
    const float* bc0 = (const float*)d_in[5];
    const float* Wg1 = (const float*)d_in[6];
    const float* bg1 = (const float*)d_in[7];
    const float* Wc1 = (const float*)d_in[8];
    const float* bc1 = (const float*)d_in[9];
    const float* smb = (const float*)d_in[10];
    float* out = (float*)d_out;

    float *pgx0,*pcx0,*poutT,*pTg0,*pTg1,*pTc0,*pTc1;
    bf16 *pxh,*pxl,*poh,*pol,*pwgh,*pwgl,*pwch,*pwcl,*peh,*pel;
    cudaGetSymbolAddress((void**)&pgx0,  g_gx0);
    cudaGetSymbolAddress((void**)&pcx0,  g_cx0);
    cudaGetSymbolAddress((void**)&poutT, g_outT);
    cudaGetSymbolAddress((void**)&pTg0,  g_Tg0);
    cudaGetSymbolAddress((void**)&pTg1,  g_Tg1);
    cudaGetSymbolAddress((void**)&pTc0,  g_Tc0);
    cudaGetSymbolAddress((void**)&pTc1,  g_Tc1);
    cudaGetSymbolAddress((void**)&pxh,   g_xh);
    cudaGetSymbolAddress((void**)&pxl,   g_xl);
    cudaGetSymbolAddress((void**)&poh,   g_oh);
    cudaGetSymbolAddress((void**)&pol,   g_ol);
    cudaGetSymbolAddress((void**)&pwgh,  g_wgh);
    cudaGetSymbolAddress((void**)&pwgl,  g_wgl);
    cudaGetSymbolAddress((void**)&pwch,  g_wch);
    cudaGetSymbolAddress((void**)&pwcl,  g_wcl);
    cudaGetSymbolAddress((void**)&peh,   g_eh);
    cudaGetSymbolAddress((void**)&pel,   g_el);

    static bool attr_set = false;
    if (!attr_set){
        cudaFuncSetAttribute(rnn_persist, cudaFuncAttributeMaxDynamicSharedMemorySize, SMF*4);
        cudaFuncSetAttribute(hgemm<true>,  cudaFuncAttributeMaxDynamicSharedMemorySize, HSM);
        cudaFuncSetAttribute(hgemm<false>, cudaFuncAttributeMaxDynamicSharedMemorySize, HSM);
        attr_set = true;
    }

    // recurrence weights -> [n][k] fp32
    tr_w<<<dim3(32,64), dim3(32,8)>>>(Wg0, 1024, H2, pTg0, H);
    tr_w<<<dim3(64,64), dim3(32,8)>>>(Wg1, 0,    H2, pTg1, H2);
    tr_w<<<dim3(32,32), dim3(32,8)>>>(Wc0, 1024, H,  pTc0, H);
    tr_w<<<dim3(64,32), dim3(32,8)>>>(Wc1, 0,    H,  pTc1, H2);

    // bf16 planes
    embed2<<<MROWS, 256>>>(idx, emb, pxh, pxl);
    tr_split<<<dim3(32,64), dim3(32,8)>>>(Wg0, H2, pwgh, pwgl);
    tr_split<<<dim3(32,32), dim3(32,8)>>>(Wc0, H,  pwch, pwcl);
    econv<<<VPAD, 256>>>(emb, peh, pel);

    // layer-0 x-projections on tensor cores -> [t][m][n]
    hgemm<true><<<dim3(H2/64, MROWS/128), 256, HSM>>>(pxh, pxl, pwgh, pwgl, nullptr, pgx0, H2);
    hgemm<true><<<dim3(H/64,  MROWS/128), 256, HSM>>>(pxh, pxl, pwch, pwcl, nullptr, pcx0, H);

    // recurrence (fp32 persistent kernel)
    rnn_persist<<<NB, NTHR, SMF*4>>>(bg0, bc0, bg1, bc1);

    // logits on tensor cores
    outconv<<<MROWS, 256>>>(poutT, poh, pol);
    hgemm<false><<<dim3(VPAD/64, MROWS/128), 256, HSM>>>(poh, pol, peh, pel, smb, out, VOCAB);
}